// round 12
// baseline (speedup 1.0000x reference)
#include <cuda_runtime.h>
#include <cuda_fp16.h>
#include <cstdint>

#define DI __device__ __forceinline__

static constexpr int BATCH = 8, SEQ = 2048, DIM = 512;
static constexpr int MROWS = BATCH * SEQ;            // 16384
static constexpr int BM = 128, BN = 256, BK = 32;    // BK in halves
static constexpr int NTHREADS = 512;                 // 16 warps: 2(m) x 8(n), 64x32 tiles
static constexpr int STAGES = 4;
static constexpr int SH = 40;                        // smem row stride (halves)

// per stage: A 128*40 + B 256*40 halves = 15360 halves = 30720 B
static constexpr int BUF_HALVES = (BM + BN) * SH;
static constexpr int SMEM_BYTES = STAGES * BUF_HALVES * 2;   // 122880

// ---- scratch (static device; 128B aligned) ----
__device__ __align__(128) __half g_QIN[MROWS * DIM];
__device__ __align__(128) __half g_VIN[MROWS * DIM];
__device__ __align__(128) __half g_WT [3 * DIM * DIM];     // W^T [w][u][d]
__device__ __align__(128) __half g_Q  [MROWS * DIM];
__device__ __align__(128) __half g_K  [MROWS * DIM];
__device__ __align__(128) __half g_VT [BATCH * DIM * SEQ]; // [b][u][s]
__device__ __align__(128) __half g_S  [BATCH * SEQ * SEQ]; // exp(scores)
__device__ __align__(128) float  g_RS [MROWS];             // row sums

// ---- helpers ----
DI void cpa16(uint32_t s, const void* g) {
    asm volatile("cp.async.cg.shared.global [%0], [%1], 16;" :: "r"(s), "l"(g));
}
DI void cp_commit() { asm volatile("cp.async.commit_group;" ::: "memory"); }
template <int N> DI void cp_wait() {
    asm volatile("cp.async.wait_group %0;" :: "n"(N) : "memory");
}
DI void mma16(float* c, const uint32_t* a, const uint32_t* b) {
    asm volatile(
        "mma.sync.aligned.m16n8k16.row.col.f32.f16.f16.f32 "
        "{%0,%1,%2,%3},{%4,%5,%6,%7},{%8,%9},{%0,%1,%2,%3};"
        : "+f"(c[0]), "+f"(c[1]), "+f"(c[2]), "+f"(c[3])
        : "r"(a[0]), "r"(a[1]), "r"(a[2]), "r"(a[3]), "r"(b[0]), "r"(b[1]));
}
DI uint32_t h2u(__half2 h) { return *reinterpret_cast<uint32_t*>(&h); }

// ------------------------------------------------------------------
// C tile [BM x BN] at (m0, n0) of C = A * B^T. A[BM,kTot], B[BN,kTot] fp16
// K-major (pointers pre-offset). 16 warps 2x8, warp tile 64x32.
// epi: 0 = half C = rn(acc)                  (proj Q/K)
//      1 = float C = acc / rsum[m0+row]      (final context)
//      2 = V-transpose half store            (proj V)
//      3 = half C = rn(exp(scale*acc))       (scores -> P)
// ------------------------------------------------------------------
__device__ void gemm_tile(const __half* __restrict__ At, int lda,
                          const __half* __restrict__ Bt, int ldb,
                          int kTot, void* __restrict__ Cv, int ldc,
                          float scale, int m0, int n0, int epi,
                          const float* __restrict__ rsum)
{
    extern __shared__ __align__(16) __half smem[];
    const int tid  = threadIdx.x;
    const int lane = tid & 31;
    const int wid  = tid >> 5;
    const int wm   = (wid & 1) * 64;          // 2 warp rows
    const int wn   = (wid >> 1) * 32;         // 8 warp cols

    float acc[4][4][4];
    #pragma unroll
    for (int i = 0; i < 4; i++)
        #pragma unroll
        for (int j = 0; j < 4; j++)
            #pragma unroll
            for (int k = 0; k < 4; k++) acc[i][j][k] = 0.0f;

    const int NCH = kTot / BK;

    auto load_chunk = [&](int c) {
        const int k0 = c * BK;
        __half* sA = smem + (c % STAGES) * BUF_HALVES;
        uint32_t sa = (uint32_t)__cvta_generic_to_shared(sA);
        uint32_t sb = sa + BM * SH * 2;
        {                                     // A: 128 rows x 4 x 16B = 512
            int r = tid >> 2, q = tid & 3;
            cpa16(sa + r * (SH * 2) + q * 16, At + (size_t)r * lda + k0 + (q << 3));
        }
        #pragma unroll
        for (int i = 0; i < 2; i++) {         // B: 256 rows x 4 x 16B = 1024
            int e = (i << 9) + tid, r = e >> 2, q = e & 3;
            cpa16(sb + r * (SH * 2) + q * 16, Bt + (size_t)r * ldb + k0 + (q << 3));
        }
        cp_commit();
    };

    load_chunk(0); load_chunk(1); load_chunk(2);

    for (int c = 0; c < NCH; ++c) {
        if (c + 2 < NCH)      cp_wait<2>();
        else if (c + 1 < NCH) cp_wait<1>();
        else                  cp_wait<0>();
        __syncthreads();
        if (c + 3 < NCH) load_chunk(c + 3);

        const __half* sA = smem + (c % STAGES) * BUF_HALVES;
        const __half* sB = sA + BM * SH;

        #pragma unroll
        for (int ks = 0; ks < 2; ks++) {      // two k16 steps per 32-half chunk
            const int co = ks * 16 + 2 * (lane & 3);

            uint32_t a[4][4];
            #pragma unroll
            for (int mf = 0; mf < 4; mf++) {
                const __half* p = sA + (wm + mf * 16 + (lane >> 2)) * SH + co;
                a[mf][0] = *(const uint32_t*)p;
                a[mf][1] = *(const uint32_t*)(p + 8 * SH);
                a[mf][2] = *(const uint32_t*)(p + 8);
                a[mf][3] = *(const uint32_t*)(p + 8 * SH + 8);
            }
            uint32_t b[4][2];
            #pragma unroll
            for (int nf = 0; nf < 4; nf++) {
                const __half* p = sB + (wn + nf * 8 + (lane >> 2)) * SH + co;
                b[nf][0] = *(const uint32_t*)p;
                b[nf][1] = *(const uint32_t*)(p + 8);
            }
            #pragma unroll
            for (int mf = 0; mf < 4; mf++)
                #pragma unroll
                for (int nf = 0; nf < 4; nf++)
                    mma16(acc[mf][nf], a[mf], b[nf]);
        }
    }

    // ---- epilogue ----
    #pragma unroll
    for (int mf = 0; mf < 4; mf++) {
        const int row = wm + mf * 16 + (lane >> 2);
        float s0 = scale, s1 = scale;
        if (epi == 1) {
            s0 = __frcp_rn(rsum[m0 + row]);
            s1 = __frcp_rn(rsum[m0 + row + 8]);
        }
        #pragma unroll
        for (int nf = 0; nf < 4; nf++) {
            const int col = wn + nf * 8 + 2 * (lane & 3);
            const float* a4 = acc[mf][nf];
            if (epi == 2) {
                __half* C = (__half*)Cv;
                const int mg0 = m0 + row, b0 = mg0 >> 11, s0i = mg0 & 2047;
                const int mg1 = mg0 + 8,  b1 = mg1 >> 11, s1i = mg1 & 2047;
                const int u = n0 + col;
                C[((size_t)(b0 * 512 + u)) * 2048 + s0i]     = __float2half_rn(a4[0]);
                C[((size_t)(b0 * 512 + u + 1)) * 2048 + s0i] = __float2half_rn(a4[1]);
                C[((size_t)(b1 * 512 + u)) * 2048 + s1i]     = __float2half_rn(a4[2]);
                C[((size_t)(b1 * 512 + u + 1)) * 2048 + s1i] = __float2half_rn(a4[3]);
            } else if (epi == 3) {
                __half* C = (__half*)Cv;
                float e0 = __expf(fmaxf(a4[0] * scale, -20.0f));
                float e1 = __expf(fmaxf(a4[1] * scale, -20.0f));
                float e2 = __expf(fmaxf(a4[2] * scale, -20.0f));
                float e3 = __expf(fmaxf(a4[3] * scale, -20.0f));
                __half2 v0 = __floats2half2_rn(e0, e1);
                __half2 v1 = __floats2half2_rn(e2, e3);
                *(__half2*)&C[(size_t)(m0 + row) * ldc + n0 + col]     = v0;
                *(__half2*)&C[(size_t)(m0 + row + 8) * ldc + n0 + col] = v1;
            } else if (epi == 0) {
                __half* C = (__half*)Cv;
                __half2 v0 = __floats2half2_rn(a4[0], a4[1]);
                __half2 v1 = __floats2half2_rn(a4[2], a4[3]);
                *(__half2*)&C[(size_t)(m0 + row) * ldc + n0 + col]     = v0;
                *(__half2*)&C[(size_t)(m0 + row + 8) * ldc + n0 + col] = v1;
            } else {
                float* C = (float*)Cv;
                float2 v0 = make_float2(a4[0] * s0, a4[1] * s0);
                float2 v1 = make_float2(a4[2] * s1, a4[3] * s1);
                *(float2*)&C[(size_t)(m0 + row) * ldc + n0 + col]     = v0;
                *(float2*)&C[(size_t)(m0 + row + 8) * ldc + n0 + col] = v1;
            }
        }
    }
}

// ------------------------------------------------------------------
__global__ void __launch_bounds__(256) k_round(const float* __restrict__ q,
                                               const float* __restrict__ v)
{
    const int i = blockIdx.x * 256 + threadIdx.x;      // float4 index
    const float4* src = (blockIdx.y == 0) ? (const float4*)q : (const float4*)v;
    __half* dst = (blockIdx.y == 0) ? g_QIN : g_VIN;
    float4 x = src[i];
    __half2 h0 = __floats2half2_rn(x.x, x.y);
    __half2 h1 = __floats2half2_rn(x.z, x.w);
    *(uint2*)&dst[(size_t)i * 4] = make_uint2(h2u(h0), h2u(h1));
}

__global__ void __launch_bounds__(256) k_wt(const float* __restrict__ W1,
                                            const float* __restrict__ W2,
                                            const float* __restrict__ W3)
{
    int i = blockIdx.x * 256 + threadIdx.x;            // 3*512*512
    int w = i >> 18, r = i & 262143, d = r >> 9, u = r & 511;
    const float* W = (w == 0) ? W1 : (w == 1) ? W2 : W3;
    g_WT[(size_t)w * 262144 + u * 512 + d] = __float2half_rn(W[d * 512 + u]);
}

__global__ void __launch_bounds__(NTHREADS, 1) k_proj()
{
    const int z = blockIdx.z, m0 = blockIdx.x * BM, n0 = blockIdx.y * BN;
    const __half* A = ((z == 0) ? g_QIN : g_VIN) + (size_t)m0 * DIM;
    const __half* B = g_WT + (size_t)z * DIM * DIM + (size_t)n0 * DIM;
    if (z == 2)
        gemm_tile(A, DIM, B, DIM, DIM, g_VT, 0, 1.0f, m0, n0, 2, nullptr);
    else
        gemm_tile(A, DIM, B, DIM, DIM, (z == 0) ? g_Q : g_K, DIM, 1.0f, m0, n0, 0, nullptr);
}

__global__ void __launch_bounds__(NTHREADS, 1) k_score()
{
    const int b = blockIdx.z, m0 = blockIdx.x * BM, n0 = blockIdx.y * BN;
    gemm_tile(g_Q + (size_t)b * SEQ * DIM + (size_t)m0 * DIM, DIM,
              g_K + (size_t)b * SEQ * DIM + (size_t)n0 * DIM, DIM,
              DIM, g_S + (size_t)b * SEQ * SEQ, SEQ,
              0.044194173824159216f, m0, n0, 3, nullptr);
}

__global__ void __launch_bounds__(256) k_rowsum()
{
    __shared__ float rs[8];
    const size_t row = (size_t)blockIdx.x * SEQ;
    const int t = threadIdx.x;
    uint4 u = *(const uint4*)&g_S[row + (size_t)t * 8];
    float s = 0.0f;
    {
        float2 f;
        f = __half22float2(*(__half2*)&u.x); s += f.x + f.y;
        f = __half22float2(*(__half2*)&u.y); s += f.x + f.y;
        f = __half22float2(*(__half2*)&u.z); s += f.x + f.y;
        f = __half22float2(*(__half2*)&u.w); s += f.x + f.y;
    }
    #pragma unroll
    for (int o = 16; o; o >>= 1) s += __shfl_xor_sync(0xffffffffu, s, o);
    if ((t & 31) == 0) rs[t >> 5] = s;
    __syncthreads();
    if (t == 0) {
        g_RS[blockIdx.x] = rs[0] + rs[1] + rs[2] + rs[3] + rs[4] + rs[5] + rs[6] + rs[7];
    }
}

__global__ void __launch_bounds__(NTHREADS, 1) k_ctx(float* __restrict__ out)
{
    const int b = blockIdx.z, m0 = blockIdx.x * BM, n0 = blockIdx.y * BN;
    gemm_tile(g_S + (size_t)b * SEQ * SEQ + (size_t)m0 * SEQ, SEQ,
              g_VT + ((size_t)b * DIM + n0) * SEQ, SEQ,
              SEQ, out + (size_t)b * SEQ * DIM, DIM, 1.0f, m0, n0, 1,
              g_RS + (size_t)b * SEQ);
}

// ------------------------------------------------------------------
extern "C" void kernel_launch(void* const* d_in, const int* in_sizes, int n_in,
                              void* d_out, int out_size)
{
    (void)in_sizes; (void)n_in; (void)out_size;
    const float* query = (const float*)d_in[0];
    const float* value = (const float*)d_in[1];
    const float* W1    = (const float*)d_in[2];
    const float* W2    = (const float*)d_in[3];
    const float* W3    = (const float*)d_in[4];
    float* out = (float*)d_out;

    static bool attr_done = false;
    if (!attr_done) {
        cudaFuncSetAttribute(k_proj,  cudaFuncAttributeMaxDynamicSharedMemorySize, SMEM_BYTES);
        cudaFuncSetAttribute(k_score, cudaFuncAttributeMaxDynamicSharedMemorySize, SMEM_BYTES);
        cudaFuncSetAttribute(k_ctx,   cudaFuncAttributeMaxDynamicSharedMemorySize, SMEM_BYTES);
        attr_done = true;
    }

    k_round<<<dim3(MROWS * DIM / 4 / 256, 2), 256>>>(query, value);
    k_wt<<<3 * DIM * DIM / 256, 256>>>(W1, W2, W3);
    k_proj<<<dim3(MROWS / BM, DIM / BN, 3), NTHREADS, SMEM_BYTES>>>();
    k_score<<<dim3(SEQ / BM, SEQ / BN, BATCH), NTHREADS, SMEM_BYTES>>>();
    k_rowsum<<<MROWS, 256>>>();
    k_ctx<<<dim3(SEQ / BM, DIM / BN, BATCH), NTHREADS, SMEM_BYTES>>>(out);
}

// round 13
// speedup vs baseline: 1.2395x; 1.2395x over previous
#include <cuda_runtime.h>
#include <cuda_fp16.h>
#include <cstdint>

#define DI __device__ __forceinline__

static constexpr int BATCH = 8, SEQ = 2048, DIM = 512;
static constexpr int MROWS = BATCH * SEQ;            // 16384
static constexpr int BM = 128, BN = 256, BK = 64;    // BK in halves
static constexpr int STAGES = 3;
static constexpr int SH = 72;                        // smem row stride (halves)

// per stage: (128+256)*72 halves = 27648 halves = 55296 B
static constexpr int BUF_HALVES = (BM + BN) * SH;
static constexpr int SMEM_BYTES = STAGES * BUF_HALVES * 2;   // 165888

// ---- scratch (static device; 128B aligned) ----
__device__ __align__(128) __half g_QIN[MROWS * DIM];
__device__ __align__(128) __half g_VIN[MROWS * DIM];
__device__ __align__(128) __half g_WT [3 * DIM * DIM];     // W^T [w][u][d]
__device__ __align__(128) __half g_Q  [MROWS * DIM];
__device__ __align__(128) __half g_K  [MROWS * DIM];
__device__ __align__(128) __half g_VT [BATCH * DIM * SEQ]; // [b][u][s]
__device__ __align__(128) __half g_S  [BATCH * SEQ * SEQ]; // exp(scores)
__device__ __align__(128) float  g_RS [MROWS];             // row sums

// ---- helpers ----
DI void cpa16(uint32_t s, const void* g) {
    asm volatile("cp.async.cg.shared.global [%0], [%1], 16;" :: "r"(s), "l"(g));
}
DI void cp_commit() { asm volatile("cp.async.commit_group;" ::: "memory"); }
template <int N> DI void cp_wait() {
    asm volatile("cp.async.wait_group %0;" :: "n"(N) : "memory");
}
DI void mma16(float* c, const uint32_t* a, const uint32_t* b) {
    asm volatile(
        "mma.sync.aligned.m16n8k16.row.col.f32.f16.f16.f32 "
        "{%0,%1,%2,%3},{%4,%5,%6,%7},{%8,%9},{%0,%1,%2,%3};"
        : "+f"(c[0]), "+f"(c[1]), "+f"(c[2]), "+f"(c[3])
        : "r"(a[0]), "r"(a[1]), "r"(a[2]), "r"(a[3]), "r"(b[0]), "r"(b[1]));
}
DI void ldsm4(uint32_t* r, uint32_t addr) {
    asm volatile("ldmatrix.sync.aligned.m8n8.x4.shared.b16 {%0,%1,%2,%3}, [%4];"
                 : "=r"(r[0]), "=r"(r[1]), "=r"(r[2]), "=r"(r[3]) : "r"(addr));
}
DI uint32_t h2u(__half2 h) { return *reinterpret_cast<uint32_t*>(&h); }

// ------------------------------------------------------------------
// C tile [BM x BN] at (m0, n0) of C = A * B^T. A[BM,kTot], B[BN,kTot] fp16
// K-major (pointers pre-offset). 8 warps 2x4, warp tile 64x64, ldmatrix feeds.
// epi: 0 = half C = rn(acc)                  (proj Q/K)
//      1 = float C = acc / rsum[m0+row]      (final context)
//      2 = V-transpose half store            (proj V)
//      3 = half C = rn(exp(scale*acc))       (scores -> P)
// ------------------------------------------------------------------
__device__ void gemm_tile(const __half* __restrict__ At, int lda,
                          const __half* __restrict__ Bt, int ldb,
                          int kTot, void* __restrict__ Cv, int ldc,
                          float scale, int m0, int n0, int epi,
                          const float* __restrict__ rsum)
{
    extern __shared__ __align__(16) __half smem[];
    const int tid  = threadIdx.x;
    const int lane = tid & 31;
    const int wid  = tid >> 5;
    const int wm   = (wid & 1) * 64;
    const int wn   = (wid >> 1) * 64;

    float acc[4][8][4];
    #pragma unroll
    for (int i = 0; i < 4; i++)
        #pragma unroll
        for (int j = 0; j < 8; j++)
            #pragma unroll
            for (int k = 0; k < 4; k++) acc[i][j][k] = 0.0f;

    const int NCH = kTot / BK;
    const uint32_t sbase = (uint32_t)__cvta_generic_to_shared(smem);

    // ldmatrix per-lane row/col (halves) within tile, constant across chunks
    const int arow = wm + (lane & 15);           // + mf*16
    const int acol = (lane >> 4) << 3;           // 0 or 8, + ks*16
    const int brow = wn + (lane & 7) + ((lane >> 4) << 3);   // + pair*16
    const int bcol = ((lane >> 3) & 1) << 3;     // 0 or 8, + ks*16

    auto load_chunk = [&](int c) {
        const int k0 = c * BK;
        uint32_t sa = sbase + (c % STAGES) * (BUF_HALVES * 2);
        uint32_t sb = sa + BM * SH * 2;
        #pragma unroll
        for (int i = 0; i < 4; i++) {        // A: 128 rows x 8 x 16B = 1024
            int e = (i << 8) + tid, r = e >> 3, q = e & 7;
            cpa16(sa + r * (SH * 2) + q * 16, At + (size_t)r * lda + k0 + (q << 3));
        }
        #pragma unroll
        for (int i = 0; i < 8; i++) {        // B: 256 rows x 8 x 16B = 2048
            int e = (i << 8) + tid, r = e >> 3, q = e & 7;
            cpa16(sb + r * (SH * 2) + q * 16, Bt + (size_t)r * ldb + k0 + (q << 3));
        }
        cp_commit();
    };

    load_chunk(0);
    if (NCH > 1) load_chunk(1);

    for (int c = 0; c < NCH; ++c) {
        if (c + 1 < NCH) cp_wait<1>();
        else             cp_wait<0>();
        __syncthreads();
        if (c + 2 < NCH) load_chunk(c + 2);

        const uint32_t stgA = sbase + (c % STAGES) * (BUF_HALVES * 2);
        const uint32_t stgB = stgA + BM * SH * 2;

        #pragma unroll
        for (int ks = 0; ks < 4; ks++) {     // four k16 steps per 64-half chunk
            const int co = ks << 4;

            uint32_t a[4][4];
            #pragma unroll
            for (int mf = 0; mf < 4; mf++)
                ldsm4(a[mf], stgA + (uint32_t)(((arow + mf * 16) * SH + acol + co) * 2));

            uint32_t b[4][4];                // pair p holds nf=2p (regs 0,1), nf=2p+1 (2,3)
            #pragma unroll
            for (int p = 0; p < 4; p++)
                ldsm4(b[p], stgB + (uint32_t)(((brow + p * 16) * SH + bcol + co) * 2));

            #pragma unroll
            for (int mf = 0; mf < 4; mf++)
                #pragma unroll
                for (int nf = 0; nf < 8; nf++)
                    mma16(acc[mf][nf], a[mf], &b[nf >> 1][(nf & 1) << 1]);
        }
    }

    // ---- epilogue ----
    #pragma unroll
    for (int mf = 0; mf < 4; mf++) {
        const int row = wm + mf * 16 + (lane >> 2);
        float s0 = scale, s1 = scale;
        if (epi == 1) {
            s0 = __frcp_rn(rsum[m0 + row]);
            s1 = __frcp_rn(rsum[m0 + row + 8]);
        }
        #pragma unroll
        for (int nf = 0; nf < 8; nf++) {
            const int col = wn + nf * 8 + 2 * (lane & 3);
            const float* a4 = acc[mf][nf];
            if (epi == 2) {
                __half* C = (__half*)Cv;
                const int mg0 = m0 + row, b0 = mg0 >> 11, s0i = mg0 & 2047;
                const int mg1 = mg0 + 8,  b1 = mg1 >> 11, s1i = mg1 & 2047;
                const int u = n0 + col;
                C[((size_t)(b0 * 512 + u)) * 2048 + s0i]     = __float2half_rn(a4[0]);
                C[((size_t)(b0 * 512 + u + 1)) * 2048 + s0i] = __float2half_rn(a4[1]);
                C[((size_t)(b1 * 512 + u)) * 2048 + s1i]     = __float2half_rn(a4[2]);
                C[((size_t)(b1 * 512 + u + 1)) * 2048 + s1i] = __float2half_rn(a4[3]);
            } else if (epi == 3) {
                __half* C = (__half*)Cv;
                float e0 = __expf(fmaxf(a4[0] * scale, -20.0f));
                float e1 = __expf(fmaxf(a4[1] * scale, -20.0f));
                float e2 = __expf(fmaxf(a4[2] * scale, -20.0f));
                float e3 = __expf(fmaxf(a4[3] * scale, -20.0f));
                __half2 v0 = __floats2half2_rn(e0, e1);
                __half2 v1 = __floats2half2_rn(e2, e3);
                *(__half2*)&C[(size_t)(m0 + row) * ldc + n0 + col]     = v0;
                *(__half2*)&C[(size_t)(m0 + row + 8) * ldc + n0 + col] = v1;
            } else if (epi == 0) {
                __half* C = (__half*)Cv;
                __half2 v0 = __floats2half2_rn(a4[0], a4[1]);
                __half2 v1 = __floats2half2_rn(a4[2], a4[3]);
                *(__half2*)&C[(size_t)(m0 + row) * ldc + n0 + col]     = v0;
                *(__half2*)&C[(size_t)(m0 + row + 8) * ldc + n0 + col] = v1;
            } else {
                float* C = (float*)Cv;
                float2 v0 = make_float2(a4[0] * s0, a4[1] * s0);
                float2 v1 = make_float2(a4[2] * s1, a4[3] * s1);
                *(float2*)&C[(size_t)(m0 + row) * ldc + n0 + col]     = v0;
                *(float2*)&C[(size_t)(m0 + row + 8) * ldc + n0 + col] = v1;
            }
        }
    }
}

// ------------------------------------------------------------------
__global__ void __launch_bounds__(256) k_round(const float* __restrict__ q,
                                               const float* __restrict__ v)
{
    const int i = blockIdx.x * 256 + threadIdx.x;      // float4 index
    const float4* src = (blockIdx.y == 0) ? (const float4*)q : (const float4*)v;
    __half* dst = (blockIdx.y == 0) ? g_QIN : g_VIN;
    float4 x = src[i];
    __half2 h0 = __floats2half2_rn(x.x, x.y);
    __half2 h1 = __floats2half2_rn(x.z, x.w);
    *(uint2*)&dst[(size_t)i * 4] = make_uint2(h2u(h0), h2u(h1));
}

__global__ void __launch_bounds__(256) k_wt(const float* __restrict__ W1,
                                            const float* __restrict__ W2,
                                            const float* __restrict__ W3)
{
    int i = blockIdx.x * 256 + threadIdx.x;            // 3*512*512
    int w = i >> 18, r = i & 262143, d = r >> 9, u = r & 511;
    const float* W = (w == 0) ? W1 : (w == 1) ? W2 : W3;
    g_WT[(size_t)w * 262144 + u * 512 + d] = __float2half_rn(W[d * 512 + u]);
}

__global__ void __launch_bounds__(256, 1) k_proj()
{
    const int z = blockIdx.z, m0 = blockIdx.x * BM, n0 = blockIdx.y * BN;
    const __half* A = ((z == 0) ? g_QIN : g_VIN) + (size_t)m0 * DIM;
    const __half* B = g_WT + (size_t)z * DIM * DIM + (size_t)n0 * DIM;
    if (z == 2)
        gemm_tile(A, DIM, B, DIM, DIM, g_VT, 0, 1.0f, m0, n0, 2, nullptr);
    else
        gemm_tile(A, DIM, B, DIM, DIM, (z == 0) ? g_Q : g_K, DIM, 1.0f, m0, n0, 0, nullptr);
}

__global__ void __launch_bounds__(256, 1) k_score()
{
    const int b = blockIdx.z, m0 = blockIdx.x * BM, n0 = blockIdx.y * BN;
    gemm_tile(g_Q + (size_t)b * SEQ * DIM + (size_t)m0 * DIM, DIM,
              g_K + (size_t)b * SEQ * DIM + (size_t)n0 * DIM, DIM,
              DIM, g_S + (size_t)b * SEQ * SEQ, SEQ,
              0.044194173824159216f, m0, n0, 3, nullptr);
}

__global__ void __launch_bounds__(256) k_rowsum()
{
    __shared__ float rs[8];
    const size_t row = (size_t)blockIdx.x * SEQ;
    const int t = threadIdx.x;
    uint4 u = *(const uint4*)&g_S[row + (size_t)t * 8];
    float s = 0.0f;
    {
        float2 f;
        f = __half22float2(*(__half2*)&u.x); s += f.x + f.y;
        f = __half22float2(*(__half2*)&u.y); s += f.x + f.y;
        f = __half22float2(*(__half2*)&u.z); s += f.x + f.y;
        f = __half22float2(*(__half2*)&u.w); s += f.x + f.y;
    }
    #pragma unroll
    for (int o = 16; o; o >>= 1) s += __shfl_xor_sync(0xffffffffu, s, o);
    if ((t & 31) == 0) rs[t >> 5] = s;
    __syncthreads();
    if (t == 0) {
        g_RS[blockIdx.x] = rs[0] + rs[1] + rs[2] + rs[3] + rs[4] + rs[5] + rs[6] + rs[7];
    }
}

__global__ void __launch_bounds__(256, 1) k_ctx(float* __restrict__ out)
{
    const int b = blockIdx.z, m0 = blockIdx.x * BM, n0 = blockIdx.y * BN;
    gemm_tile(g_S + (size_t)b * SEQ * SEQ + (size_t)m0 * SEQ, SEQ,
              g_VT + ((size_t)b * DIM + n0) * SEQ, SEQ,
              SEQ, out + (size_t)b * SEQ * DIM, DIM, 1.0f, m0, n0, 1,
              g_RS + (size_t)b * SEQ);
}

// ------------------------------------------------------------------
extern "C" void kernel_launch(void* const* d_in, const int* in_sizes, int n_in,
                              void* d_out, int out_size)
{
    (void)in_sizes; (void)n_in; (void)out_size;
    const float* query = (const float*)d_in[0];
    const float* value = (const float*)d_in[1];
    const float* W1    = (const float*)d_in[2];
    const float* W2    = (const float*)d_in[3];
    const float* W3    = (const float*)d_in[4];
    float* out = (float*)d_out;

    static bool attr_done = false;
    if (!attr_done) {
        cudaFuncSetAttribute(k_proj,  cudaFuncAttributeMaxDynamicSharedMemorySize, SMEM_BYTES);
        cudaFuncSetAttribute(k_score, cudaFuncAttributeMaxDynamicSharedMemorySize, SMEM_BYTES);
        cudaFuncSetAttribute(k_ctx,   cudaFuncAttributeMaxDynamicSharedMemorySize, SMEM_BYTES);
        attr_done = true;
    }

    k_round<<<dim3(MROWS * DIM / 4 / 256, 2), 256>>>(query, value);
    k_wt<<<3 * DIM * DIM / 256, 256>>>(W1, W2, W3);
    k_proj<<<dim3(MROWS / BM, DIM / BN, 3), 256, SMEM_BYTES>>>();
    k_score<<<dim3(SEQ / BM, SEQ / BN, BATCH), 256, SMEM_BYTES>>>();
    k_rowsum<<<MROWS, 256>>>();
    k_ctx<<<dim3(SEQ / BM, DIM / BN, BATCH), 256, SMEM_BYTES>>>(out);
}

// round 14
// speedup vs baseline: 1.3423x; 1.0830x over previous
#include <cuda_runtime.h>
#include <cuda_fp16.h>
#include <cstdint>

#define DI __device__ __forceinline__

static constexpr int BATCH = 8, SEQ = 2048, DIM = 512;
static constexpr int MROWS = BATCH * SEQ;            // 16384
static constexpr int BM = 128, BN = 128, BK = 64;    // BK in halves
static constexpr int NTHREADS = 128;                 // 4 warps, 2x2 of 64x64 tiles
static constexpr int STAGES = 3;
static constexpr int SH = 72;                        // smem row stride (halves)

// per stage: (128+128)*72 halves = 18432 halves = 36864 B
static constexpr int BUF_HALVES = (BM + BN) * SH;
static constexpr int SMEM_BYTES = STAGES * BUF_HALVES * 2;   // 110592 (x2 CTAs = 221KB)

// ---- scratch (static device; 128B aligned) ----
__device__ __align__(128) __half g_QIN[MROWS * DIM];
__device__ __align__(128) __half g_VIN[MROWS * DIM];
__device__ __align__(128) __half g_WT [3 * DIM * DIM];     // W^T [w][u][d]
__device__ __align__(128) __half g_Q  [MROWS * DIM];
__device__ __align__(128) __half g_K  [MROWS * DIM];
__device__ __align__(128) __half g_VT [BATCH * DIM * SEQ]; // [b][u][s]
__device__ __align__(128) __half g_S  [BATCH * SEQ * SEQ]; // exp(scores)
__device__ __align__(128) float  g_RS [MROWS];             // row sums

// ---- helpers ----
DI void cpa16(uint32_t s, const void* g) {
    asm volatile("cp.async.cg.shared.global [%0], [%1], 16;" :: "r"(s), "l"(g));
}
DI void cp_commit() { asm volatile("cp.async.commit_group;" ::: "memory"); }
template <int N> DI void cp_wait() {
    asm volatile("cp.async.wait_group %0;" :: "n"(N) : "memory");
}
DI void mma16(float* c, const uint32_t* a, const uint32_t* b) {
    asm volatile(
        "mma.sync.aligned.m16n8k16.row.col.f32.f16.f16.f32 "
        "{%0,%1,%2,%3},{%4,%5,%6,%7},{%8,%9},{%0,%1,%2,%3};"
        : "+f"(c[0]), "+f"(c[1]), "+f"(c[2]), "+f"(c[3])
        : "r"(a[0]), "r"(a[1]), "r"(a[2]), "r"(a[3]), "r"(b[0]), "r"(b[1]));
}
DI void ldsm4(uint32_t* r, uint32_t addr) {
    asm volatile("ldmatrix.sync.aligned.m8n8.x4.shared.b16 {%0,%1,%2,%3}, [%4];"
                 : "=r"(r[0]), "=r"(r[1]), "=r"(r[2]), "=r"(r[3]) : "r"(addr));
}
DI uint32_t h2u(__half2 h) { return *reinterpret_cast<uint32_t*>(&h); }

// ------------------------------------------------------------------
// C tile [BM x BN] at (m0, n0) of C = A * B^T. A[BM,kTot], B[BN,kTot] fp16
// K-major (pointers pre-offset). 4 warps 2x2, warp tile 64x64, ldmatrix feeds.
// 2 CTAs/SM so chunk-boundary stalls interleave across CTAs.
// epi: 0 = half C = rn(acc)                  (proj Q/K)
//      1 = float C = acc / rsum[m0+row]      (final context)
//      2 = V-transpose half store            (proj V)
//      3 = half C = rn(exp(scale*acc))       (scores -> P)
// ------------------------------------------------------------------
__device__ void gemm_tile(const __half* __restrict__ At, int lda,
                          const __half* __restrict__ Bt, int ldb,
                          int kTot, void* __restrict__ Cv, int ldc,
                          float scale, int m0, int n0, int epi,
                          const float* __restrict__ rsum)
{
    extern __shared__ __align__(16) __half smem[];
    const int tid  = threadIdx.x;
    const int lane = tid & 31;
    const int wid  = tid >> 5;
    const int wm   = (wid & 1) * 64;          // 2 warp rows
    const int wn   = (wid >> 1) * 64;         // 2 warp cols

    float acc[4][8][4];
    #pragma unroll
    for (int i = 0; i < 4; i++)
        #pragma unroll
        for (int j = 0; j < 8; j++)
            #pragma unroll
            for (int k = 0; k < 4; k++) acc[i][j][k] = 0.0f;

    const int NCH = kTot / BK;
    const uint32_t sbase = (uint32_t)__cvta_generic_to_shared(smem);

    // ldmatrix per-lane row/col (halves) within tile, constant across chunks
    const int arow = wm + (lane & 15);           // + mf*16
    const int acol = (lane >> 4) << 3;           // 0 or 8, + ks*16
    const int brow = wn + (lane & 7) + ((lane >> 4) << 3);   // + pair*16
    const int bcol = ((lane >> 3) & 1) << 3;     // 0 or 8, + ks*16

    auto load_chunk = [&](int c) {
        const int k0 = c * BK;
        uint32_t sa = sbase + (c % STAGES) * (BUF_HALVES * 2);
        uint32_t sb = sa + BM * SH * 2;
        #pragma unroll
        for (int i = 0; i < 8; i++) {        // A: 128 rows x 8 x 16B = 1024
            int e = (i << 7) + tid, r = e >> 3, q = e & 7;
            cpa16(sa + r * (SH * 2) + q * 16, At + (size_t)r * lda + k0 + (q << 3));
        }
        #pragma unroll
        for (int i = 0; i < 8; i++) {        // B: 128 rows x 8 x 16B = 1024
            int e = (i << 7) + tid, r = e >> 3, q = e & 7;
            cpa16(sb + r * (SH * 2) + q * 16, Bt + (size_t)r * ldb + k0 + (q << 3));
        }
        cp_commit();
    };

    load_chunk(0);
    if (NCH > 1) load_chunk(1);

    for (int c = 0; c < NCH; ++c) {
        if (c + 1 < NCH) cp_wait<1>();
        else             cp_wait<0>();
        __syncthreads();
        if (c + 2 < NCH) load_chunk(c + 2);

        const uint32_t stgA = sbase + (c % STAGES) * (BUF_HALVES * 2);
        const uint32_t stgB = stgA + BM * SH * 2;

        #pragma unroll
        for (int ks = 0; ks < 4; ks++) {     // four k16 steps per 64-half chunk
            const int co = ks << 4;

            uint32_t a[4][4];
            #pragma unroll
            for (int mf = 0; mf < 4; mf++)
                ldsm4(a[mf], stgA + (uint32_t)(((arow + mf * 16) * SH + acol + co) * 2));

            uint32_t b[4][4];                // pair p holds nf=2p (regs 0,1), nf=2p+1 (2,3)
            #pragma unroll
            for (int p = 0; p < 4; p++)
                ldsm4(b[p], stgB + (uint32_t)(((brow + p * 16) * SH + bcol + co) * 2));

            #pragma unroll
            for (int mf = 0; mf < 4; mf++)
                #pragma unroll
                for (int nf = 0; nf < 8; nf++)
                    mma16(acc[mf][nf], a[mf], &b[nf >> 1][(nf & 1) << 1]);
        }
    }

    // ---- epilogue ----
    #pragma unroll
    for (int mf = 0; mf < 4; mf++) {
        const int row = wm + mf * 16 + (lane >> 2);
        float s0 = scale, s1 = scale;
        if (epi == 1) {
            s0 = __frcp_rn(rsum[m0 + row]);
            s1 = __frcp_rn(rsum[m0 + row + 8]);
        }
        #pragma unroll
        for (int nf = 0; nf < 8; nf++) {
            const int col = wn + nf * 8 + 2 * (lane & 3);
            const float* a4 = acc[mf][nf];
            if (epi == 2) {
                __half* C = (__half*)Cv;
                const int mg0 = m0 + row, b0 = mg0 >> 11, s0i = mg0 & 2047;
                const int mg1 = mg0 + 8,  b1 = mg1 >> 11, s1i = mg1 & 2047;
                const int u = n0 + col;
                C[((size_t)(b0 * 512 + u)) * 2048 + s0i]     = __float2half_rn(a4[0]);
                C[((size_t)(b0 * 512 + u + 1)) * 2048 + s0i] = __float2half_rn(a4[1]);
                C[((size_t)(b1 * 512 + u)) * 2048 + s1i]     = __float2half_rn(a4[2]);
                C[((size_t)(b1 * 512 + u + 1)) * 2048 + s1i] = __float2half_rn(a4[3]);
            } else if (epi == 3) {
                __half* C = (__half*)Cv;
                float e0 = __expf(fmaxf(a4[0] * scale, -20.0f));
                float e1 = __expf(fmaxf(a4[1] * scale, -20.0f));
                float e2 = __expf(fmaxf(a4[2] * scale, -20.0f));
                float e3 = __expf(fmaxf(a4[3] * scale, -20.0f));
                __half2 v0 = __floats2half2_rn(e0, e1);
                __half2 v1 = __floats2half2_rn(e2, e3);
                *(__half2*)&C[(size_t)(m0 + row) * ldc + n0 + col]     = v0;
                *(__half2*)&C[(size_t)(m0 + row + 8) * ldc + n0 + col] = v1;
            } else if (epi == 0) {
                __half* C = (__half*)Cv;
                __half2 v0 = __floats2half2_rn(a4[0], a4[1]);
                __half2 v1 = __floats2half2_rn(a4[2], a4[3]);
                *(__half2*)&C[(size_t)(m0 + row) * ldc + n0 + col]     = v0;
                *(__half2*)&C[(size_t)(m0 + row + 8) * ldc + n0 + col] = v1;
            } else {
                float* C = (float*)Cv;
                float2 v0 = make_float2(a4[0] * s0, a4[1] * s0);
                float2 v1 = make_float2(a4[2] * s1, a4[3] * s1);
                *(float2*)&C[(size_t)(m0 + row) * ldc + n0 + col]     = v0;
                *(float2*)&C[(size_t)(m0 + row + 8) * ldc + n0 + col] = v1;
            }
        }
    }
}

// ------------------------------------------------------------------
__global__ void __launch_bounds__(256) k_round(const float* __restrict__ q,
                                               const float* __restrict__ v)
{
    const int i = blockIdx.x * 256 + threadIdx.x;      // float4 index
    const float4* src = (blockIdx.y == 0) ? (const float4*)q : (const float4*)v;
    __half* dst = (blockIdx.y == 0) ? g_QIN : g_VIN;
    float4 x = src[i];
    __half2 h0 = __floats2half2_rn(x.x, x.y);
    __half2 h1 = __floats2half2_rn(x.z, x.w);
    *(uint2*)&dst[(size_t)i * 4] = make_uint2(h2u(h0), h2u(h1));
}

__global__ void __launch_bounds__(256) k_wt(const float* __restrict__ W1,
                                            const float* __restrict__ W2,
                                            const float* __restrict__ W3)
{
    int i = blockIdx.x * 256 + threadIdx.x;            // 3*512*512
    int w = i >> 18, r = i & 262143, d = r >> 9, u = r & 511;
    const float* W = (w == 0) ? W1 : (w == 1) ? W2 : W3;
    g_WT[(size_t)w * 262144 + u * 512 + d] = __float2half_rn(W[d * 512 + u]);
}

__global__ void __launch_bounds__(NTHREADS, 2) k_proj()
{
    const int z = blockIdx.z, m0 = blockIdx.x * BM, n0 = blockIdx.y * BN;
    const __half* A = ((z == 0) ? g_QIN : g_VIN) + (size_t)m0 * DIM;
    const __half* B = g_WT + (size_t)z * DIM * DIM + (size_t)n0 * DIM;
    if (z == 2)
        gemm_tile(A, DIM, B, DIM, DIM, g_VT, 0, 1.0f, m0, n0, 2, nullptr);
    else
        gemm_tile(A, DIM, B, DIM, DIM, (z == 0) ? g_Q : g_K, DIM, 1.0f, m0, n0, 0, nullptr);
}

__global__ void __launch_bounds__(NTHREADS, 2) k_score()
{
    const int b = blockIdx.z, m0 = blockIdx.x * BM, n0 = blockIdx.y * BN;
    gemm_tile(g_Q + (size_t)b * SEQ * DIM + (size_t)m0 * DIM, DIM,
              g_K + (size_t)b * SEQ * DIM + (size_t)n0 * DIM, DIM,
              DIM, g_S + (size_t)b * SEQ * SEQ, SEQ,
              0.044194173824159216f, m0, n0, 3, nullptr);
}

__global__ void __launch_bounds__(256) k_rowsum()
{
    __shared__ float rs[8];
    const size_t row = (size_t)blockIdx.x * SEQ;
    const int t = threadIdx.x;
    uint4 u = *(const uint4*)&g_S[row + (size_t)t * 8];
    float s = 0.0f;
    {
        float2 f;
        f = __half22float2(*(__half2*)&u.x); s += f.x + f.y;
        f = __half22float2(*(__half2*)&u.y); s += f.x + f.y;
        f = __half22float2(*(__half2*)&u.z); s += f.x + f.y;
        f = __half22float2(*(__half2*)&u.w); s += f.x + f.y;
    }
    #pragma unroll
    for (int o = 16; o; o >>= 1) s += __shfl_xor_sync(0xffffffffu, s, o);
    if ((t & 31) == 0) rs[t >> 5] = s;
    __syncthreads();
    if (t == 0) {
        g_RS[blockIdx.x] = rs[0] + rs[1] + rs[2] + rs[3] + rs[4] + rs[5] + rs[6] + rs[7];
    }
}

__global__ void __launch_bounds__(NTHREADS, 2) k_ctx(float* __restrict__ out)
{
    const int b = blockIdx.z, m0 = blockIdx.x * BM, n0 = blockIdx.y * BN;
    gemm_tile(g_S + (size_t)b * SEQ * SEQ + (size_t)m0 * SEQ, SEQ,
              g_VT + ((size_t)b * DIM + n0) * SEQ, SEQ,
              SEQ, out + (size_t)b * SEQ * DIM, DIM, 1.0f, m0, n0, 1,
              g_RS + (size_t)b * SEQ);
}

// ------------------------------------------------------------------
extern "C" void kernel_launch(void* const* d_in, const int* in_sizes, int n_in,
                              void* d_out, int out_size)
{
    (void)in_sizes; (void)n_in; (void)out_size;
    const float* query = (const float*)d_in[0];
    const float* value = (const float*)d_in[1];
    const float* W1    = (const float*)d_in[2];
    const float* W2    = (const float*)d_in[3];
    const float* W3    = (const float*)d_in[4];
    float* out = (float*)d_out;

    static bool attr_done = false;
    if (!attr_done) {
        cudaFuncSetAttribute(k_proj,  cudaFuncAttributeMaxDynamicSharedMemorySize, SMEM_BYTES);
        cudaFuncSetAttribute(k_score, cudaFuncAttributeMaxDynamicSharedMemorySize, SMEM_BYTES);
        cudaFuncSetAttribute(k_ctx,   cudaFuncAttributeMaxDynamicSharedMemorySize, SMEM_BYTES);
        attr_done = true;
    }

    k_round<<<dim3(MROWS * DIM / 4 / 256, 2), 256>>>(query, value);
    k_wt<<<3 * DIM * DIM / 256, 256>>>(W1, W2, W3);
    k_proj<<<dim3(MROWS / BM, DIM / BN, 3), NTHREADS, SMEM_BYTES>>>();
    k_score<<<dim3(SEQ / BM, SEQ / BN, BATCH), NTHREADS, SMEM_BYTES>>>();
    k_rowsum<<<MROWS, 256>>>();
    k_ctx<<<dim3(SEQ / BM, DIM / BN, BATCH), NTHREADS, SMEM_BYTES>>>(out);
}

// round 16
// speedup vs baseline: 1.3795x; 1.0278x over previous
#include <cuda_runtime.h>
#include <cuda_fp16.h>
#include <cstdint>

#define DI __device__ __forceinline__

static constexpr int BATCH = 8, SEQ = 2048, DIM = 512;
static constexpr int MROWS = BATCH * SEQ;            // 16384
static constexpr int BM = 128, BN = 128, BK = 64;    // BK in halves
static constexpr int NTHREADS = 128;                 // 4 warps, 2x2 of 64x64 tiles
static constexpr int STAGES = 3;
static constexpr int SH = 72;                        // smem row stride (halves)
static constexpr int NXT = SEQ / BN;                 // 16 score n-tiles per row

// per stage: (128+128)*72 halves = 18432 halves = 36864 B
static constexpr int BUF_HALVES = (BM + BN) * SH;
static constexpr int SMEM_BYTES = STAGES * BUF_HALVES * 2;   // 110592 (x2 CTAs = 221KB)

// ---- scratch (static device; 128B aligned) ----
__device__ __align__(128) __half g_QIN[MROWS * DIM];
__device__ __align__(128) __half g_VIN[MROWS * DIM];
__device__ __align__(128) __half g_WT [3 * DIM * DIM];     // W^T [w][u][d]
__device__ __align__(128) __half g_Q  [MROWS * DIM];
__device__ __align__(128) __half g_K  [MROWS * DIM];
__device__ __align__(128) __half g_VT [BATCH * DIM * SEQ]; // [b][u][s]
__device__ __align__(128) __half g_S  [BATCH * SEQ * SEQ]; // exp(scores)
__device__ __align__(128) float  g_RSP[MROWS * NXT];       // per-tile partial row sums
__device__ __align__(128) float  g_RS [MROWS];             // row sums

// ---- helpers ----
DI void cpa16(uint32_t s, const void* g) {
    asm volatile("cp.async.cg.shared.global [%0], [%1], 16;" :: "r"(s), "l"(g));
}
DI void cp_commit() { asm volatile("cp.async.commit_group;" ::: "memory"); }
template <int N> DI void cp_wait() {
    asm volatile("cp.async.wait_group %0;" :: "n"(N) : "memory");
}
DI void mma16(float* c, const uint32_t* a, const uint32_t* b) {
    asm volatile(
        "mma.sync.aligned.m16n8k16.row.col.f32.f16.f16.f32 "
        "{%0,%1,%2,%3},{%4,%5,%6,%7},{%8,%9},{%0,%1,%2,%3};"
        : "+f"(c[0]), "+f"(c[1]), "+f"(c[2]), "+f"(c[3])
        : "r"(a[0]), "r"(a[1]), "r"(a[2]), "r"(a[3]), "r"(b[0]), "r"(b[1]));
}
DI void ldsm4(uint32_t* r, uint32_t addr) {
    asm volatile("ldmatrix.sync.aligned.m8n8.x4.shared.b16 {%0,%1,%2,%3}, [%4];"
                 : "=r"(r[0]), "=r"(r[1]), "=r"(r[2]), "=r"(r[3]) : "r"(addr));
}
DI uint32_t h2u(__half2 h) { return *reinterpret_cast<uint32_t*>(&h); }

// ------------------------------------------------------------------
// C tile [BM x BN] at (m0, n0) of C = A * B^T. A[BM,kTot], B[BN,kTot] fp16
// K-major (pointers pre-offset). 4 warps 2x2, warp tile 64x64, ldmatrix feeds.
// 2 CTAs/SM so chunk-boundary stalls interleave across CTAs.
// m0/n0 are LOCAL tile offsets within C. gm0 = global row base (epi 3 g_RSP
// indexing only; pass m0 otherwise).
// epi: 0 = half C = rn(acc)                  (proj Q/K)
//      1 = float C = acc / rsum[m0+row]      (final context)
//      2 = V-transpose half store            (proj V)
//      3 = half C = rn(exp(scale*acc))       (scores -> P) + partial row sums
// ------------------------------------------------------------------
__device__ void gemm_tile(const __half* __restrict__ At, int lda,
                          const __half* __restrict__ Bt, int ldb,
                          int kTot, void* __restrict__ Cv, int ldc,
                          float scale, int m0, int n0, int epi,
                          const float* __restrict__ rsum, int gm0)
{
    extern __shared__ __align__(16) __half smem[];
    const int tid  = threadIdx.x;
    const int lane = tid & 31;
    const int wid  = tid >> 5;
    const int wm   = (wid & 1) * 64;          // 2 warp rows
    const int wn   = (wid >> 1) * 64;         // 2 warp cols

    float acc[4][8][4];
    #pragma unroll
    for (int i = 0; i < 4; i++)
        #pragma unroll
        for (int j = 0; j < 8; j++)
            #pragma unroll
            for (int k = 0; k < 4; k++) acc[i][j][k] = 0.0f;

    const int NCH = kTot / BK;
    const uint32_t sbase = (uint32_t)__cvta_generic_to_shared(smem);

    // ldmatrix per-lane row/col (halves) within tile, constant across chunks
    const int arow = wm + (lane & 15);           // + mf*16
    const int acol = (lane >> 4) << 3;           // 0 or 8, + ks*16
    const int brow = wn + (lane & 7) + ((lane >> 4) << 3);   // + pair*16
    const int bcol = ((lane >> 3) & 1) << 3;     // 0 or 8, + ks*16

    auto load_chunk = [&](int c) {
        const int k0 = c * BK;
        uint32_t sa = sbase + (c % STAGES) * (BUF_HALVES * 2);
        uint32_t sb = sa + BM * SH * 2;
        #pragma unroll
        for (int i = 0; i < 8; i++) {        // A: 128 rows x 8 x 16B = 1024
            int e = (i << 7) + tid, r = e >> 3, q = e & 7;
            cpa16(sa + r * (SH * 2) + q * 16, At + (size_t)r * lda + k0 + (q << 3));
        }
        #pragma unroll
        for (int i = 0; i < 8; i++) {        // B: 128 rows x 8 x 16B = 1024
            int e = (i << 7) + tid, r = e >> 3, q = e & 7;
            cpa16(sb + r * (SH * 2) + q * 16, Bt + (size_t)r * ldb + k0 + (q << 3));
        }
        cp_commit();
    };

    load_chunk(0);
    if (NCH > 1) load_chunk(1);

    for (int c = 0; c < NCH; ++c) {
        if (c + 1 < NCH) cp_wait<1>();
        else             cp_wait<0>();
        __syncthreads();
        if (c + 2 < NCH) load_chunk(c + 2);

        const uint32_t stgA = sbase + (c % STAGES) * (BUF_HALVES * 2);
        const uint32_t stgB = stgA + BM * SH * 2;

        #pragma unroll
        for (int ks = 0; ks < 4; ks++) {     // four k16 steps per 64-half chunk
            const int co = ks << 4;

            uint32_t a[4][4];
            #pragma unroll
            for (int mf = 0; mf < 4; mf++)
                ldsm4(a[mf], stgA + (uint32_t)(((arow + mf * 16) * SH + acol + co) * 2));

            uint32_t b[4][4];                // pair p holds nf=2p (regs 0,1), nf=2p+1 (2,3)
            #pragma unroll
            for (int p = 0; p < 4; p++)
                ldsm4(b[p], stgB + (uint32_t)(((brow + p * 16) * SH + bcol + co) * 2));

            #pragma unroll
            for (int mf = 0; mf < 4; mf++)
                #pragma unroll
                for (int nf = 0; nf < 8; nf++)
                    mma16(acc[mf][nf], a[mf], &b[nf >> 1][(nf & 1) << 1]);
        }
    }

    // ---- epilogue ----
    float sp0[4] = {0.f, 0.f, 0.f, 0.f};      // epi==3 partial row sums (row)
    float sp1[4] = {0.f, 0.f, 0.f, 0.f};      // (row + 8)
    if (epi == 3) __syncthreads();            // stage smem dead; reused below

    #pragma unroll
    for (int mf = 0; mf < 4; mf++) {
        const int row = wm + mf * 16 + (lane >> 2);
        float s0 = scale, s1 = scale;
        if (epi == 1) {
            s0 = __frcp_rn(rsum[m0 + row]);
            s1 = __frcp_rn(rsum[m0 + row + 8]);
        }
        #pragma unroll
        for (int nf = 0; nf < 8; nf++) {
            const int col = wn + nf * 8 + 2 * (lane & 3);
            const float* a4 = acc[mf][nf];
            if (epi == 2) {
                __half* C = (__half*)Cv;
                const int mg0 = m0 + row, b0 = mg0 >> 11, s0i = mg0 & 2047;
                const int mg1 = mg0 + 8,  b1 = mg1 >> 11, s1i = mg1 & 2047;
                const int u = n0 + col;
                C[((size_t)(b0 * 512 + u)) * 2048 + s0i]     = __float2half_rn(a4[0]);
                C[((size_t)(b0 * 512 + u + 1)) * 2048 + s0i] = __float2half_rn(a4[1]);
                C[((size_t)(b1 * 512 + u)) * 2048 + s1i]     = __float2half_rn(a4[2]);
                C[((size_t)(b1 * 512 + u + 1)) * 2048 + s1i] = __float2half_rn(a4[3]);
            } else if (epi == 3) {
                __half* C = (__half*)Cv;
                float e0 = __expf(fmaxf(a4[0] * scale, -20.0f));
                float e1 = __expf(fmaxf(a4[1] * scale, -20.0f));
                float e2 = __expf(fmaxf(a4[2] * scale, -20.0f));
                float e3 = __expf(fmaxf(a4[3] * scale, -20.0f));
                __half2 v0 = __floats2half2_rn(e0, e1);
                __half2 v1 = __floats2half2_rn(e2, e3);
                // accumulate partial row sums from the ROUNDED stored values
                float2 f0 = __half22float2(v0);
                float2 f1 = __half22float2(v1);
                sp0[mf] += f0.x + f0.y;
                sp1[mf] += f1.x + f1.y;
                *(__half2*)&C[(size_t)(m0 + row) * ldc + n0 + col]     = v0;
                *(__half2*)&C[(size_t)(m0 + row + 8) * ldc + n0 + col] = v1;
            } else if (epi == 0) {
                __half* C = (__half*)Cv;
                __half2 v0 = __floats2half2_rn(a4[0], a4[1]);
                __half2 v1 = __floats2half2_rn(a4[2], a4[3]);
                *(__half2*)&C[(size_t)(m0 + row) * ldc + n0 + col]     = v0;
                *(__half2*)&C[(size_t)(m0 + row + 8) * ldc + n0 + col] = v1;
            } else {
                float* C = (float*)Cv;
                float2 v0 = make_float2(a4[0] * s0, a4[1] * s0);
                float2 v1 = make_float2(a4[2] * s1, a4[3] * s1);
                *(float2*)&C[(size_t)(m0 + row) * ldc + n0 + col]     = v0;
                *(float2*)&C[(size_t)(m0 + row + 8) * ldc + n0 + col] = v1;
            }
        }
    }

    if (epi == 3) {
        // reduce partial sums across the 4 lanes of each quad (cols), then
        // across the 2 warp columns via smem; write per-tile partials.
        float* rsp = (float*)smem;               // [128][2] floats
        #pragma unroll
        for (int mf = 0; mf < 4; mf++) {
            #pragma unroll
            for (int o = 1; o <= 2; o <<= 1) {
                sp0[mf] += __shfl_xor_sync(0xffffffffu, sp0[mf], o);
                sp1[mf] += __shfl_xor_sync(0xffffffffu, sp1[mf], o);
            }
        }
        const int wnIdx = wid >> 1;              // warp column 0/1
        if ((lane & 3) == 0) {
            #pragma unroll
            for (int mf = 0; mf < 4; mf++) {
                int r0 = wm + mf * 16 + (lane >> 2);
                rsp[r0 * 2 + wnIdx]       = sp0[mf];
                rsp[(r0 + 8) * 2 + wnIdx] = sp1[mf];
            }
        }
        __syncthreads();
        const int xt = n0 >> 7;                  // n-tile index (BN=128)
        // tid covers all 128 rows; gm0 = global row base
        g_RSP[(size_t)(gm0 + tid) * NXT + xt] = rsp[tid * 2] + rsp[tid * 2 + 1];
    }
}

// ------------------------------------------------------------------
// merged prep: fp32 -> fp16 rounding of inputs + W transpose
__global__ void __launch_bounds__(256) k_prep(const float* __restrict__ q,
                                              const float* __restrict__ v,
                                              const float* __restrict__ W1,
                                              const float* __restrict__ W2,
                                              const float* __restrict__ W3)
{
    const int bx = blockIdx.x;
    if (bx < 16384) {
        const int half = bx >> 13;                       // 0:query 1:value
        const int i = (bx & 8191) * 256 + threadIdx.x;   // float4 index
        const float4* src = (half == 0) ? (const float4*)q : (const float4*)v;
        __half* dst = (half == 0) ? g_QIN : g_VIN;
        float4 x = src[i];
        __half2 h0 = __floats2half2_rn(x.x, x.y);
        __half2 h1 = __floats2half2_rn(x.z, x.w);
        *(uint2*)&dst[(size_t)i * 4] = make_uint2(h2u(h0), h2u(h1));
    } else {
        const int i = (bx - 16384) * 256 + threadIdx.x;  // 3*512*512 elements
        const int w = i >> 18, r = i & 262143, d = r >> 9, u = r & 511;
        const float* W = (w == 0) ? W1 : (w == 1) ? W2 : W3;
        g_WT[(size_t)w * 262144 + u * 512 + d] = __float2half_rn(W[d * 512 + u]);
    }
}

__global__ void __launch_bounds__(NTHREADS, 2) k_proj()
{
    const int z = blockIdx.z, m0 = blockIdx.x * BM, n0 = blockIdx.y * BN;
    const __half* A = ((z == 0) ? g_QIN : g_VIN) + (size_t)m0 * DIM;
    const __half* B = g_WT + (size_t)z * DIM * DIM + (size_t)n0 * DIM;
    if (z == 2)
        gemm_tile(A, DIM, B, DIM, DIM, g_VT, 0, 1.0f, m0, n0, 2, nullptr, m0);
    else
        gemm_tile(A, DIM, B, DIM, DIM, (z == 0) ? g_Q : g_K, DIM, 1.0f, m0, n0, 0, nullptr, m0);
}

__global__ void __launch_bounds__(NTHREADS, 2) k_score()
{
    const int b = blockIdx.z, m0 = blockIdx.x * BM, n0 = blockIdx.y * BN;
    gemm_tile(g_Q + (size_t)b * SEQ * DIM + (size_t)m0 * DIM, DIM,
              g_K + (size_t)b * SEQ * DIM + (size_t)n0 * DIM, DIM,
              DIM, g_S + (size_t)b * SEQ * SEQ, SEQ,
              0.044194173824159216f, m0, n0, 3, nullptr, b * SEQ + m0);
}

// reduce the 16 per-tile partials per row into g_RS
__global__ void __launch_bounds__(256) k_rsred()
{
    const int r = blockIdx.x * 256 + threadIdx.x;        // 64 blocks x 256
    const float4* p = (const float4*)&g_RSP[(size_t)r * NXT];
    float4 a = p[0], b = p[1], c = p[2], d = p[3];
    g_RS[r] = (((a.x + a.y) + (a.z + a.w)) + ((b.x + b.y) + (b.z + b.w)))
            + (((c.x + c.y) + (c.z + c.w)) + ((d.x + d.y) + (d.z + d.w)));
}

__global__ void __launch_bounds__(NTHREADS, 2) k_ctx(float* __restrict__ out)
{
    const int b = blockIdx.z, m0 = blockIdx.x * BM, n0 = blockIdx.y * BN;
    gemm_tile(g_S + (size_t)b * SEQ * SEQ + (size_t)m0 * SEQ, SEQ,
              g_VT + ((size_t)b * DIM + n0) * SEQ, SEQ,
              SEQ, out + (size_t)b * SEQ * DIM, DIM, 1.0f, m0, n0, 1,
              g_RS + (size_t)b * SEQ, m0);
}

// ------------------------------------------------------------------
extern "C" void kernel_launch(void* const* d_in, const int* in_sizes, int n_in,
                              void* d_out, int out_size)
{
    (void)in_sizes; (void)n_in; (void)out_size;
    const float* query = (const float*)d_in[0];
    const float* value = (const float*)d_in[1];
    const float* W1    = (const float*)d_in[2];
    const float* W2    = (const float*)d_in[3];
    const float* W3    = (const float*)d_in[4];
    float* out = (float*)d_out;

    static bool attr_done = false;
    if (!attr_done) {
        cudaFuncSetAttribute(k_proj,  cudaFuncAttributeMaxDynamicSharedMemorySize, SMEM_BYTES);
        cudaFuncSetAttribute(k_score, cudaFuncAttributeMaxDynamicSharedMemorySize, SMEM_BYTES);
        cudaFuncSetAttribute(k_ctx,   cudaFuncAttributeMaxDynamicSharedMemorySize, SMEM_BYTES);
        attr_done = true;
    }

    k_prep<<<16384 + 3072, 256>>>(query, value, W1, W2, W3);
    k_proj<<<dim3(MROWS / BM, DIM / BN, 3), NTHREADS, SMEM_BYTES>>>();
    k_score<<<dim3(SEQ / BM, SEQ / BN, BATCH), NTHREADS, SMEM_BYTES>>>();
    k_rsred<<<MROWS / 256, 256>>>();
    k_ctx<<<dim3(SEQ / BM, DIM / BN, BATCH), NTHREADS, SMEM_BYTES>>>(out);
}

// round 17
// speedup vs baseline: 1.4044x; 1.0180x over previous
#include <cuda_runtime.h>
#include <cuda_fp16.h>
#include <cstdint>

#define DI __device__ __forceinline__

static constexpr int BATCH = 8, SEQ = 2048, DIM = 512;
static constexpr int MROWS = BATCH * SEQ;            // 16384
static constexpr int BM = 128, BN = 128, BK = 64;    // BK in halves
static constexpr int NTHREADS = 128;                 // 4 warps, 2x2 of 64x64 tiles
static constexpr int STAGES = 3;
static constexpr int SH = 72;                        // smem row stride (halves)
static constexpr int NXT = SEQ / BN;                 // 16 score n-tiles per row

// per stage: (128+128)*72 halves = 18432 halves = 36864 B
static constexpr int BUF_HALVES = (BM + BN) * SH;
static constexpr int STAGE_BYTES = STAGES * BUF_HALVES * 2;  // 110592
static constexpr int SMEM_BYTES = STAGE_BYTES + 512;         // + rsinv slab (x2 CTAs fits)

// ---- scratch (static device; 128B aligned) ----
__device__ __align__(128) __half g_QIN[MROWS * DIM];
__device__ __align__(128) __half g_VIN[MROWS * DIM];
__device__ __align__(128) __half g_WT [3 * DIM * DIM];     // W^T [w][u][d]
__device__ __align__(128) __half g_Q  [MROWS * DIM];
__device__ __align__(128) __half g_K  [MROWS * DIM];
__device__ __align__(128) __half g_VT [BATCH * DIM * SEQ]; // [b][u][s]
__device__ __align__(128) __half g_S  [BATCH * SEQ * SEQ]; // exp(scores)
__device__ __align__(128) float  g_RSP[MROWS * NXT];       // per-tile partial row sums

// ---- helpers ----
DI void cpa16(uint32_t s, const void* g) {
    asm volatile("cp.async.cg.shared.global [%0], [%1], 16;" :: "r"(s), "l"(g));
}
DI void cp_commit() { asm volatile("cp.async.commit_group;" ::: "memory"); }
template <int N> DI void cp_wait() {
    asm volatile("cp.async.wait_group %0;" :: "n"(N) : "memory");
}
DI void mma16(float* c, const uint32_t* a, const uint32_t* b) {
    asm volatile(
        "mma.sync.aligned.m16n8k16.row.col.f32.f16.f16.f32 "
        "{%0,%1,%2,%3},{%4,%5,%6,%7},{%8,%9},{%0,%1,%2,%3};"
        : "+f"(c[0]), "+f"(c[1]), "+f"(c[2]), "+f"(c[3])
        : "r"(a[0]), "r"(a[1]), "r"(a[2]), "r"(a[3]), "r"(b[0]), "r"(b[1]));
}
DI void ldsm4(uint32_t* r, uint32_t addr) {
    asm volatile("ldmatrix.sync.aligned.m8n8.x4.shared.b16 {%0,%1,%2,%3}, [%4];"
                 : "=r"(r[0]), "=r"(r[1]), "=r"(r[2]), "=r"(r[3]) : "r"(addr));
}
DI uint32_t h2u(__half2 h) { return *reinterpret_cast<uint32_t*>(&h); }

// ------------------------------------------------------------------
// C tile [BM x BN] at (m0, n0) of C = A * B^T. A[BM,kTot], B[BN,kTot] fp16
// K-major (pointers pre-offset). 4 warps 2x2, warp tile 64x64, ldmatrix feeds.
// 2 CTAs/SM so chunk-boundary stalls interleave across CTAs.
// m0/n0 are LOCAL tile offsets within C. gm0 = global row base (epi 3 g_RSP
// indexing only). rsinv (epi 1): smem array of 128 per-row INVERSE sums.
// epi: 0 = half C = rn(acc)                  (proj Q/K)
//      1 = float C = acc * rsinv[row]        (final context)
//      2 = V-transpose half store            (proj V)
//      3 = half C = rn(exp(scale*acc))       (scores -> P) + partial row sums
// ------------------------------------------------------------------
__device__ void gemm_tile(const __half* __restrict__ At, int lda,
                          const __half* __restrict__ Bt, int ldb,
                          int kTot, void* __restrict__ Cv, int ldc,
                          float scale, int m0, int n0, int epi,
                          const float* rsinv, int gm0)
{
    extern __shared__ __align__(16) __half smem[];
    const int tid  = threadIdx.x;
    const int lane = tid & 31;
    const int wid  = tid >> 5;
    const int wm   = (wid & 1) * 64;          // 2 warp rows
    const int wn   = (wid >> 1) * 64;         // 2 warp cols

    float acc[4][8][4];
    #pragma unroll
    for (int i = 0; i < 4; i++)
        #pragma unroll
        for (int j = 0; j < 8; j++)
            #pragma unroll
            for (int k = 0; k < 4; k++) acc[i][j][k] = 0.0f;

    const int NCH = kTot / BK;
    const uint32_t sbase = (uint32_t)__cvta_generic_to_shared(smem);

    // ldmatrix per-lane row/col (halves) within tile, constant across chunks
    const int arow = wm + (lane & 15);           // + mf*16
    const int acol = (lane >> 4) << 3;           // 0 or 8, + ks*16
    const int brow = wn + (lane & 7) + ((lane >> 4) << 3);   // + pair*16
    const int bcol = ((lane >> 3) & 1) << 3;     // 0 or 8, + ks*16

    auto load_chunk = [&](int c) {
        const int k0 = c * BK;
        uint32_t sa = sbase + (c % STAGES) * (BUF_HALVES * 2);
        uint32_t sb = sa + BM * SH * 2;
        #pragma unroll
        for (int i = 0; i < 8; i++) {        // A: 128 rows x 8 x 16B = 1024
            int e = (i << 7) + tid, r = e >> 3, q = e & 7;
            cpa16(sa + r * (SH * 2) + q * 16, At + (size_t)r * lda + k0 + (q << 3));
        }
        #pragma unroll
        for (int i = 0; i < 8; i++) {        // B: 128 rows x 8 x 16B = 1024
            int e = (i << 7) + tid, r = e >> 3, q = e & 7;
            cpa16(sb + r * (SH * 2) + q * 16, Bt + (size_t)r * ldb + k0 + (q << 3));
        }
        cp_commit();
    };

    load_chunk(0);
    if (NCH > 1) load_chunk(1);

    for (int c = 0; c < NCH; ++c) {
        if (c + 1 < NCH) cp_wait<1>();
        else             cp_wait<0>();
        __syncthreads();
        if (c + 2 < NCH) load_chunk(c + 2);

        const uint32_t stgA = sbase + (c % STAGES) * (BUF_HALVES * 2);
        const uint32_t stgB = stgA + BM * SH * 2;

        #pragma unroll
        for (int ks = 0; ks < 4; ks++) {     // four k16 steps per 64-half chunk
            const int co = ks << 4;

            uint32_t a[4][4];
            #pragma unroll
            for (int mf = 0; mf < 4; mf++)
                ldsm4(a[mf], stgA + (uint32_t)(((arow + mf * 16) * SH + acol + co) * 2));

            uint32_t b[4][4];                // pair p holds nf=2p (regs 0,1), nf=2p+1 (2,3)
            #pragma unroll
            for (int p = 0; p < 4; p++)
                ldsm4(b[p], stgB + (uint32_t)(((brow + p * 16) * SH + bcol + co) * 2));

            #pragma unroll
            for (int mf = 0; mf < 4; mf++)
                #pragma unroll
                for (int nf = 0; nf < 8; nf++)
                    mma16(acc[mf][nf], a[mf], &b[nf >> 1][(nf & 1) << 1]);
        }
    }

    // ---- epilogue ----
    float sp0[4] = {0.f, 0.f, 0.f, 0.f};      // epi==3 partial row sums (row)
    float sp1[4] = {0.f, 0.f, 0.f, 0.f};      // (row + 8)
    if (epi == 3) __syncthreads();            // stage smem dead; reused below

    #pragma unroll
    for (int mf = 0; mf < 4; mf++) {
        const int row = wm + mf * 16 + (lane >> 2);
        float s0 = scale, s1 = scale;
        if (epi == 1) {
            s0 = rsinv[row];
            s1 = rsinv[row + 8];
        }
        #pragma unroll
        for (int nf = 0; nf < 8; nf++) {
            const int col = wn + nf * 8 + 2 * (lane & 3);
            const float* a4 = acc[mf][nf];
            if (epi == 2) {
                __half* C = (__half*)Cv;
                const int mg0 = m0 + row, b0 = mg0 >> 11, s0i = mg0 & 2047;
                const int mg1 = mg0 + 8,  b1 = mg1 >> 11, s1i = mg1 & 2047;
                const int u = n0 + col;
                C[((size_t)(b0 * 512 + u)) * 2048 + s0i]     = __float2half_rn(a4[0]);
                C[((size_t)(b0 * 512 + u + 1)) * 2048 + s0i] = __float2half_rn(a4[1]);
                C[((size_t)(b1 * 512 + u)) * 2048 + s1i]     = __float2half_rn(a4[2]);
                C[((size_t)(b1 * 512 + u + 1)) * 2048 + s1i] = __float2half_rn(a4[3]);
            } else if (epi == 3) {
                __half* C = (__half*)Cv;
                float e0 = __expf(fmaxf(a4[0] * scale, -20.0f));
                float e1 = __expf(fmaxf(a4[1] * scale, -20.0f));
                float e2 = __expf(fmaxf(a4[2] * scale, -20.0f));
                float e3 = __expf(fmaxf(a4[3] * scale, -20.0f));
                __half2 v0 = __floats2half2_rn(e0, e1);
                __half2 v1 = __floats2half2_rn(e2, e3);
                // accumulate partial row sums from the ROUNDED stored values
                float2 f0 = __half22float2(v0);
                float2 f1 = __half22float2(v1);
                sp0[mf] += f0.x + f0.y;
                sp1[mf] += f1.x + f1.y;
                *(__half2*)&C[(size_t)(m0 + row) * ldc + n0 + col]     = v0;
                *(__half2*)&C[(size_t)(m0 + row + 8) * ldc + n0 + col] = v1;
            } else if (epi == 0) {
                __half* C = (__half*)Cv;
                __half2 v0 = __floats2half2_rn(a4[0], a4[1]);
                __half2 v1 = __floats2half2_rn(a4[2], a4[3]);
                *(__half2*)&C[(size_t)(m0 + row) * ldc + n0 + col]     = v0;
                *(__half2*)&C[(size_t)(m0 + row + 8) * ldc + n0 + col] = v1;
            } else {
                float* C = (float*)Cv;
                float2 v0 = make_float2(a4[0] * s0, a4[1] * s0);
                float2 v1 = make_float2(a4[2] * s1, a4[3] * s1);
                *(float2*)&C[(size_t)(m0 + row) * ldc + n0 + col]     = v0;
                *(float2*)&C[(size_t)(m0 + row + 8) * ldc + n0 + col] = v1;
            }
        }
    }

    if (epi == 3) {
        // reduce partial sums across the 4 lanes of each quad (cols), then
        // across the 2 warp columns via smem; write per-tile partials.
        float* rsp = (float*)smem;               // [128][2] floats
        #pragma unroll
        for (int mf = 0; mf < 4; mf++) {
            #pragma unroll
            for (int o = 1; o <= 2; o <<= 1) {
                sp0[mf] += __shfl_xor_sync(0xffffffffu, sp0[mf], o);
                sp1[mf] += __shfl_xor_sync(0xffffffffu, sp1[mf], o);
            }
        }
        const int wnIdx = wid >> 1;              // warp column 0/1
        if ((lane & 3) == 0) {
            #pragma unroll
            for (int mf = 0; mf < 4; mf++) {
                int r0 = wm + mf * 16 + (lane >> 2);
                rsp[r0 * 2 + wnIdx]       = sp0[mf];
                rsp[(r0 + 8) * 2 + wnIdx] = sp1[mf];
            }
        }
        __syncthreads();
        const int xt = n0 >> 7;                  // n-tile index (BN=128)
        // tid covers all 128 rows; gm0 = global row base
        g_RSP[(size_t)(gm0 + tid) * NXT + xt] = rsp[tid * 2] + rsp[tid * 2 + 1];
    }
}

// ------------------------------------------------------------------
// merged prep: fp32 -> fp16 rounding of inputs + smem-tiled W transpose
__global__ void __launch_bounds__(256) k_prep(const float* __restrict__ q,
                                              const float* __restrict__ v,
                                              const float* __restrict__ W1,
                                              const float* __restrict__ W2,
                                              const float* __restrict__ W3)
{
    const int bx = blockIdx.x;
    if (bx < 16384) {
        const int half = bx >> 13;                       // 0:query 1:value
        const int i = (bx & 8191) * 256 + threadIdx.x;   // float4 index
        const float4* src = (half == 0) ? (const float4*)q : (const float4*)v;
        __half* dst = (half == 0) ? g_QIN : g_VIN;
        float4 x = src[i];
        __half2 h0 = __floats2half2_rn(x.x, x.y);
        __half2 h1 = __floats2half2_rn(x.z, x.w);
        *(uint2*)&dst[(size_t)i * 4] = make_uint2(h2u(h0), h2u(h1));
    } else {
        // W transpose, 64x64 smem tiles, both sides coalesced.
        __shared__ float tile[64][65];
        const int t  = bx - 16384;                       // 0..191
        const int w  = t >> 6;                           // weight index
        const int td = (t & 63) >> 3, tu = t & 7;        // tile coords
        const int d0 = td * 64, u0 = tu * 64;
        const float* W = (w == 0) ? W1 : (w == 1) ? W2 : W3;
        #pragma unroll
        for (int i = 0; i < 16; i++) {
            int e = i * 256 + threadIdx.x;
            int dr = e >> 6, uc = e & 63;                // read: uc consecutive
            tile[dr][uc] = W[(size_t)(d0 + dr) * 512 + u0 + uc];
        }
        __syncthreads();
        #pragma unroll
        for (int i = 0; i < 16; i++) {
            int e = i * 256 + threadIdx.x;
            int ur = e >> 6, dc = e & 63;                // write: dc consecutive
            g_WT[(size_t)w * 262144 + (size_t)(u0 + ur) * 512 + d0 + dc] =
                __float2half_rn(tile[dc][ur]);
        }
    }
}

__global__ void __launch_bounds__(NTHREADS, 2) k_proj()
{
    const int z = blockIdx.z, m0 = blockIdx.x * BM, n0 = blockIdx.y * BN;
    const __half* A = ((z == 0) ? g_QIN : g_VIN) + (size_t)m0 * DIM;
    const __half* B = g_WT + (size_t)z * DIM * DIM + (size_t)n0 * DIM;
    if (z == 2)
        gemm_tile(A, DIM, B, DIM, DIM, g_VT, 0, 1.0f, m0, n0, 2, nullptr, m0);
    else
        gemm_tile(A, DIM, B, DIM, DIM, (z == 0) ? g_Q : g_K, DIM, 1.0f, m0, n0, 0, nullptr, m0);
}

__global__ void __launch_bounds__(NTHREADS, 2) k_score()
{
    const int b = blockIdx.z, m0 = blockIdx.x * BM, n0 = blockIdx.y * BN;
    gemm_tile(g_Q + (size_t)b * SEQ * DIM + (size_t)m0 * DIM, DIM,
              g_K + (size_t)b * SEQ * DIM + (size_t)n0 * DIM, DIM,
              DIM, g_S + (size_t)b * SEQ * SEQ, SEQ,
              0.044194173824159216f, m0, n0, 3, nullptr, b * SEQ + m0);
}

__global__ void __launch_bounds__(NTHREADS, 2) k_ctx(float* __restrict__ out)
{
    extern __shared__ __align__(16) __half smem[];
    const int b = blockIdx.z, m0 = blockIdx.x * BM, n0 = blockIdx.y * BN;

    // prologue: per-CTA inverse row sums from g_RSP partials -> smem slab
    float* rsinv = (float*)((char*)smem + STAGE_BYTES);   // 128 floats
    if (threadIdx.x < 128) {
        const float4* p = (const float4*)&g_RSP[(size_t)(b * SEQ + m0 + threadIdx.x) * NXT];
        float4 a = p[0], c = p[1], d = p[2], e = p[3];
        float s = (((a.x + a.y) + (a.z + a.w)) + ((c.x + c.y) + (c.z + c.w)))
                + (((d.x + d.y) + (d.z + d.w)) + ((e.x + e.y) + (e.z + e.w)));
        rsinv[threadIdx.x] = __frcp_rn(s);
    }
    __syncthreads();

    gemm_tile(g_S + (size_t)b * SEQ * SEQ + (size_t)m0 * SEQ, SEQ,
              g_VT + ((size_t)b * DIM + n0) * SEQ, SEQ,
              SEQ, out + (size_t)b * SEQ * DIM, DIM, 1.0f, m0, n0, 1,
              rsinv, m0);
}

// ------------------------------------------------------------------
extern "C" void kernel_launch(void* const* d_in, const int* in_sizes, int n_in,
                              void* d_out, int out_size)
{
    (void)in_sizes; (void)n_in; (void)out_size;
    const float* query = (const float*)d_in[0];
    const float* value = (const float*)d_in[1];
    const float* W1    = (const float*)d_in[2];
    const float* W2    = (const float*)d_in[3];
    const float* W3    = (const float*)d_in[4];
    float* out = (float*)d_out;

    static bool attr_done = false;
    if (!attr_done) {
        cudaFuncSetAttribute(k_proj,  cudaFuncAttributeMaxDynamicSharedMemorySize, SMEM_BYTES);
        cudaFuncSetAttribute(k_score, cudaFuncAttributeMaxDynamicSharedMemorySize, SMEM_BYTES);
        cudaFuncSetAttribute(k_ctx,   cudaFuncAttributeMaxDynamicSharedMemorySize, SMEM_BYTES);
        attr_done = true;
    }

    k_prep<<<16384 + 192, 256>>>(query, value, W1, W2, W3);
    k_proj<<<dim3(MROWS / BM, DIM / BN, 3), NTHREADS, SMEM_BYTES>>>();
    k_score<<<dim3(SEQ / BM, SEQ / BN, BATCH), NTHREADS, SMEM_BYTES>>>();
    k_ctx<<<dim3(SEQ / BM, DIM / BN, BATCH), NTHREADS, SMEM_BYTES>>>(out);
}